// round 17
// baseline (speedup 1.0000x reference)
#include <cuda_runtime.h>
#include <cuda_fp16.h>
#include <math.h>
#include <stdint.h>

#define N_TOT 8192
#define F_DIM 128
#define TBLK  64                 // 8192 / 128
#define NTILES (TBLK*(TBLK+1)/2) // 2080 upper-triangle tiles
#define TILEB 32768              // 128 rows x 256B (fp16), XOR-swizzled
#define SM_TOTAL (2 * TILEB)     // A + B = 64KB (also reused as fp32 stage)

// Device scratch (allocation-free rules)
__device__ __half g_xh[N_TOT * F_DIM];   // scaled normalized feats [N][F] fp16
__device__ float g_part[NTILES];
__device__ int g_flags[TBLK * 32];       // flag i at [i*32], padded to own line
__device__ unsigned int g_count = 0;

__device__ __forceinline__ uint32_t smem_u32(const void* p) {
    uint32_t a;
    asm("{ .reg .u64 t; cvta.to.shared.u64 t, %1; cvt.u32.u64 %0, t; }" : "=r"(a) : "l"(p));
    return a;
}
__device__ __forceinline__ float ex2a(float x) {
    float y; asm("ex2.approx.f32 %0, %1;" : "=f"(y) : "f"(x)); return y;
}
__device__ __forceinline__ int ld_acq(const int* p) {
    int v;
    asm volatile("ld.acquire.gpu.global.b32 %0, [%1];" : "=r"(v) : "l"(p) : "memory");
    return v;
}
#define CPA16(dst, src) \
    asm volatile("cp.async.cg.shared.global [%0], [%1], 16;" :: "r"(dst), "l"(src))

// ---------------------------------------------------------------------------
// Fused kernel: normalize (blocks 0..63) + HMMA fp16 tile + exp2-sum +
// last-block deterministic finalize. One launch total.
// ---------------------------------------------------------------------------
__global__ void __launch_bounds__(512, 2) fused_kernel(const float* __restrict__ x,
                                                       float* __restrict__ out) {
    extern __shared__ char smem[];
    const uint32_t sbase = smem_u32(smem);
    const int tid  = threadIdx.x;
    const int wid  = tid >> 5;
    const int lane = tid & 31;

    // linear tile id -> (bi, bj), bj >= bi
    const int t = blockIdx.x;
    int bi = (int)((129.0f - sqrtf(16641.0f - 8.0f * (float)t)) * 0.5f);
    while ((bi + 1) * (129 - (bi + 1)) / 2 <= t) ++bi;
    while (bi * (129 - bi) / 2 > t) --bi;
    const int bj = bi + (t - bi * (129 - bi) / 2);
    const bool diag = (bi == bj);

    // ---- Phase 0: blocks 0..63 normalize row-block t (rows t*128..t*128+127)
    if (t < TBLK) {
        float* stage = (float*)smem;                 // 128x128 fp32 = 64KB
        const int b = t >> 3, thw0 = (t & 7) * 128;
        const float* src = x + (size_t)b * 131072 + thw0;
        const int f = tid >> 2, q = tid & 3;
#pragma unroll
        for (int j = 0; j < 8; ++j) {                // thread covers one 128B line
            float4 v = *(const float4*)&src[(size_t)f * 1024 + q * 32 + j * 4];
            int r = q * 32 + j * 4;
            stage[(r + 0) * 128 + f] = v.x;
            stage[(r + 1) * 128 + f] = v.y;
            stage[(r + 2) * 128 + f] = v.z;
            stage[(r + 3) * 128 + f] = v.w;
        }
        __syncthreads();
#pragma unroll
        for (int p = 0; p < 8; ++p) {                // warp per row
            int row = p * 16 + wid;
            float4 v = *(float4*)&stage[row * 128 + lane * 4];
            float ss = v.x * v.x + v.y * v.y + v.z * v.z + v.w * v.w;
#pragma unroll
            for (int off = 16; off > 0; off >>= 1)
                ss += __shfl_xor_sync(0xFFFFFFFFu, ss, off);
            // 3.7982825 = sqrt(10 / ln 2): folds the exp2 scale into the data
            float rn = (1.0f / fmaxf(sqrtf(ss), 1e-12f)) * 3.7982825f;
            uint32_t* o = (uint32_t*)(g_xh + (size_t)(t * 128 + row) * F_DIM);
            __half2 h0 = __floats2half2_rn(v.x * rn, v.y * rn);
            __half2 h1 = __floats2half2_rn(v.z * rn, v.w * rn);
            o[2 * lane]     = *(uint32_t*)&h0;
            o[2 * lane + 1] = *(uint32_t*)&h1;
        }
        __threadfence();                              // make stores visible (gpu scope)
        __syncthreads();
        if (tid == 0)
            asm volatile("st.release.gpu.global.b32 [%0], %1;"
                         :: "l"(&g_flags[t * 32]), "r"(1) : "memory");
    }

    // ---- Phase 1: wait for the two needed row-blocks
    if (tid == 0) {
        while (ld_acq(&g_flags[bi * 32]) == 0) __nanosleep(64);
        while (ld_acq(&g_flags[bj * 32]) == 0) __nanosleep(64);
    }
    __syncthreads();

    // ---- Phase 2: cooperative tile loads (2048 x 16B chunks over 512 threads)
    {
        const char* gA = (const char*)(g_xh + (size_t)bi * 128 * F_DIM);
#pragma unroll
        for (int it = 0; it < 4; ++it) {
            int idx = it * 512 + tid;
            int r = idx >> 4, q = idx & 15;
            CPA16(sbase + r * 256 + ((q ^ (r & 7)) << 4), gA + (size_t)idx * 16);
        }
        if (!diag) {
            const char* gB = (const char*)(g_xh + (size_t)bj * 128 * F_DIM);
#pragma unroll
            for (int it = 0; it < 4; ++it) {
                int idx = it * 512 + tid;
                int r = idx >> 4, q = idx & 15;
                CPA16(sbase + TILEB + r * 256 + ((q ^ (r & 7)) << 4), gB + (size_t)idx * 16);
            }
        }
        asm volatile("cp.async.commit_group;");
        asm volatile("cp.async.wait_group 0;" ::: "memory");
    }
    __syncthreads();

    const uint32_t aBase = sbase;
    const uint32_t bBase = diag ? sbase : (sbase + TILEB);

    const int wm = (wid >> 2) * 32;   // 4x4 warp grid
    const int wn = (wid & 3) * 32;
    const int g  = lane >> 3;
    const int lr = lane & 7;
    const int lrow = lane >> 2;
    const int lcol = (lane & 3) * 2;

    uint32_t acc[2][4][2];            // f16x2 packed accumulators
#pragma unroll
    for (int mt = 0; mt < 2; ++mt)
#pragma unroll
        for (int nt = 0; nt < 4; ++nt) {
            acc[mt][nt][0] = 0u;
            acc[mt][nt][1] = 0u;
        }

#pragma unroll
    for (int kc = 0; kc < 8; ++kc) {
        const int qa = kc * 2 + (g >> 1);
        const int qb = kc * 2 + (g & 1);
        uint32_t a[2][4];
#pragma unroll
        for (int mt = 0; mt < 2; ++mt) {
            int row = wm + mt * 16 + (g & 1) * 8 + lr;   // row & 7 == lr
            uint32_t addr = aBase + row * 256 + ((qa ^ lr) << 4);
            asm volatile("ldmatrix.sync.aligned.m8n8.x4.shared.b16 {%0,%1,%2,%3}, [%4];"
                         : "=r"(a[mt][0]), "=r"(a[mt][1]), "=r"(a[mt][2]), "=r"(a[mt][3])
                         : "r"(addr));
        }
        uint32_t bf[2][4];
#pragma unroll
        for (int np = 0; np < 2; ++np) {
            int row = wn + np * 16 + (g >> 1) * 8 + lr;  // row & 7 == lr
            uint32_t addr = bBase + row * 256 + ((qb ^ lr) << 4);
            asm volatile("ldmatrix.sync.aligned.m8n8.x4.shared.b16 {%0,%1,%2,%3}, [%4];"
                         : "=r"(bf[np][0]), "=r"(bf[np][1]), "=r"(bf[np][2]), "=r"(bf[np][3])
                         : "r"(addr));
        }
#pragma unroll
        for (int mt = 0; mt < 2; ++mt)
#pragma unroll
            for (int nt = 0; nt < 4; ++nt) {
                uint32_t b0 = bf[nt >> 1][(nt & 1) * 2];
                uint32_t b1 = bf[nt >> 1][(nt & 1) * 2 + 1];
                asm volatile(
                    "mma.sync.aligned.m16n8k16.row.col.f16.f16.f16.f16 "
                    "{%0,%1}, {%2,%3,%4,%5}, {%6,%7}, {%0,%1};"
                    : "+r"(acc[mt][nt][0]), "+r"(acc[mt][nt][1])
                    : "r"(a[mt][0]), "r"(a[mt][1]), "r"(a[mt][2]), "r"(a[mt][3]),
                      "r"(b0), "r"(b1));
            }
    }

    // ---- epilogue: scale pre-folded -> bare 2^acc; skip i==j on diag tiles
    float s = 0.f;
#pragma unroll
    for (int mt = 0; mt < 2; ++mt)
#pragma unroll
        for (int nt = 0; nt < 4; ++nt)
#pragma unroll
            for (int h = 0; h < 2; ++h) {
                int r_ = wm + mt * 16 + h * 8 + lrow;
                int c0 = wn + nt * 8 + lcol;
                float2 f = __half22float2(*(__half2*)&acc[mt][nt][h]);
                if (!diag || r_ != c0)     s += ex2a(f.x);
                if (!diag || r_ != c0 + 1) s += ex2a(f.y);
            }
    if (!diag) s *= 2.f;

    __shared__ float red[16];
#pragma unroll
    for (int off = 16; off > 0; off >>= 1)
        s += __shfl_down_sync(0xFFFFFFFFu, s, off);
    if (lane == 0) red[wid] = s;
    __syncthreads();
    if (tid == 0) {
        float tsum = 0.f;
#pragma unroll
        for (int w = 0; w < 16; ++w) tsum += red[w];
        asm volatile("st.global.cg.f32 [%0], %1;" :: "l"(&g_part[t]), "f"(tsum) : "memory");
        __threadfence();
        asm volatile("red.release.gpu.global.add.u32 [%0], 1;" :: "l"(&g_count) : "memory");
    }

    // ---- Phase 3: last block does the deterministic finalize + state reset
    if (t == NTILES - 1) {
        if (tid == 0) {
            while (ld_acq((const int*)&g_count) < NTILES) __nanosleep(128);
        }
        __syncthreads();
        float fs = 0.f;
        for (int i = tid; i < NTILES; i += 512) fs += __ldcg(&g_part[i]);
#pragma unroll
        for (int off = 16; off > 0; off >>= 1)
            fs += __shfl_down_sync(0xFFFFFFFFu, fs, off);
        if (lane == 0) red[wid] = fs;
        __syncthreads();
        if (tid == 0) {
            float tot = 0.f;
#pragma unroll
            for (int w = 0; w < 16; ++w) tot += red[w];
            out[0] = logf(tot);
            g_count = 0;                       // reset for next graph replay
        }
        if (tid < TBLK) g_flags[tid * 32] = 0; // reset flags for next replay
    }
}

extern "C" void kernel_launch(void* const* d_in, const int* in_sizes, int n_in,
                              void* d_out, int out_size) {
    const float* x = (const float*)d_in[0];
    float* out = (float*)d_out;
    (void)in_sizes; (void)n_in; (void)out_size;

    cudaFuncSetAttribute(fused_kernel, cudaFuncAttributeMaxDynamicSharedMemorySize, SM_TOTAL);
    fused_kernel<<<NTILES, 512, SM_TOTAL>>>(x, out);
}